// round 5
// baseline (speedup 1.0000x reference)
#include <cuda_runtime.h>

// Problem constants (B=16, N=325, H=8, L=24, DK=DV=64)
#define L_    24
#define DK_   64
#define DV_   64
#define NT_   41600               /* tiles */
#define NB_   (NT_ / 2)           /* CTAs, 2 tiles each */
#define QK_   (L_ * DK_)          /* 1536 */
#define MS_   (L_ * L_)           /* 576  */

#define SQ  68                    /* padded stride for Q/K smem */
#define SA  28                    /* padded stride for attn smem */

static const long long CTX_ELEMS = (long long)NT_ * QK_;   // 63,897,600

__global__ __launch_bounds__(128, 5)
void satt_kernel(const float* __restrict__ Qg, const float* __restrict__ Kg,
                 const float* __restrict__ Vg, const float* __restrict__ Mg,
                 const float* __restrict__ Rg,
                 float* __restrict__ Cg, float* __restrict__ Sg)
{
    __shared__ float sQ[2][L_ * SQ];
    __shared__ float sK[2][L_ * SQ];
    __shared__ float sV[2][L_ * DV_];
    __shared__ float sA[2][L_ * SA];

    const int tid  = threadIdx.x;
    const int wid  = tid >> 5;
    const int lane = tid & 31;
    const int bid  = blockIdx.x;
    const int role = wid ^ (bid & 3);          // 0,1: QK+softmax(t0,t1); 2,3: AV(t0,t1)

    // ---------------- S0: stage Q,K,V for both tiles (all threads) ----------------
#pragma unroll
    for (int t = 0; t < 2; ++t) {
        const size_t qoff = (size_t)(2 * bid + t) * QK_;
        const float4* Q4 = reinterpret_cast<const float4*>(Qg + qoff);
        const float4* K4 = reinterpret_cast<const float4*>(Kg + qoff);
        const float4* V4 = reinterpret_cast<const float4*>(Vg + qoff);
#pragma unroll
        for (int it = 0; it < 3; ++it) {
            int e = tid + it * 128;            // 0..383
            int q = e >> 4;
            int d = (e & 15) << 2;
            *reinterpret_cast<float4*>(&sQ[t][q * SQ + d]) = Q4[e];
            *reinterpret_cast<float4*>(&sK[t][q * SQ + d]) = K4[e];
            reinterpret_cast<float4*>(sV[t])[e]            = V4[e];
        }
    }

    // QK-role warps: mask/res straight into registers (no smem round-trip)
    float rv[6][3];
    unsigned int mbits = 0;
    const int qg = lane >> 3;                  // 0..3
    const int kg = lane & 7;                   // 0..7
    const int q0 = qg * 6;
    const int k0 = kg * 3;
    if (role < 2) {
        const size_t moff = (size_t)(2 * bid + role) * MS_;
        const float* R = Rg + moff;
        const float* M = Mg + moff;
#pragma unroll
        for (int i = 0; i < 6; ++i)
#pragma unroll
            for (int j = 0; j < 3; ++j) {
                const int idx = (q0 + i) * L_ + k0 + j;
                rv[i][j] = R[idx];
                if (M[idx] > 0.5f) mbits |= 1u << (i * 3 + j);
            }
    }
    __syncthreads();

    // ---------------- P1: QK^T + epilogue + score store + softmax (warps role 0,1) ----------------
    if (role < 2) {
        const int t = role;
        float acc[6][3] = {};
#pragma unroll
        for (int d4 = 0; d4 < 16; ++d4) {
            const int d = d4 << 2;
            float4 qv[6], kv[3];
#pragma unroll
            for (int i = 0; i < 6; ++i) qv[i] = *reinterpret_cast<const float4*>(&sQ[t][(q0 + i) * SQ + d]);
#pragma unroll
            for (int j = 0; j < 3; ++j) kv[j] = *reinterpret_cast<const float4*>(&sK[t][(k0 + j) * SQ + d]);
#pragma unroll
            for (int i = 0; i < 6; ++i)
#pragma unroll
                for (int j = 0; j < 3; ++j) {
                    acc[i][j] = fmaf(qv[i].x, kv[j].x, acc[i][j]);
                    acc[i][j] = fmaf(qv[i].y, kv[j].y, acc[i][j]);
                    acc[i][j] = fmaf(qv[i].z, kv[j].z, acc[i][j]);
                    acc[i][j] = fmaf(qv[i].w, kv[j].w, acc[i][j]);
                }
        }

        // epilogue: scale + res + mask (all in registers)
#pragma unroll
        for (int i = 0; i < 6; ++i)
#pragma unroll
            for (int j = 0; j < 3; ++j) {
                float s = fmaf(acc[i][j], 0.125f, rv[i][j]);
                if (mbits & (1u << (i * 3 + j))) s = -1e9f;
                acc[i][j] = s;
            }

        // masked raw scores -> global, straight from registers
        {
            float* S = Sg + (size_t)(2 * bid + t) * MS_;
#pragma unroll
            for (int i = 0; i < 6; ++i)
#pragma unroll
                for (int j = 0; j < 3; ++j)
                    S[(q0 + i) * L_ + k0 + j] = acc[i][j];
        }

        // in-warp softmax over q (columns), butterfly across the 4 q-groups
        float mk[3], sk[3];
#pragma unroll
        for (int j = 0; j < 3; ++j) {
            float m = acc[0][j];
#pragma unroll
            for (int i = 1; i < 6; ++i) m = fmaxf(m, acc[i][j]);
            m = fmaxf(m, __shfl_xor_sync(0xffffffffu, m, 8));
            m = fmaxf(m, __shfl_xor_sync(0xffffffffu, m, 16));
            mk[j] = m;
        }
#pragma unroll
        for (int j = 0; j < 3; ++j) {
            float s = 0.0f;
#pragma unroll
            for (int i = 0; i < 6; ++i) {
                acc[i][j] = __expf(acc[i][j] - mk[j]);
                s += acc[i][j];
            }
            s += __shfl_xor_sync(0xffffffffu, s, 8);
            s += __shfl_xor_sync(0xffffffffu, s, 16);
            sk[j] = __fdividef(1.0f, s);
        }
#pragma unroll
        for (int i = 0; i < 6; ++i)
#pragma unroll
            for (int j = 0; j < 3; ++j)
                sA[t][(q0 + i) * SA + k0 + j] = acc[i][j] * sk[j];
    }
    __syncthreads();

    // ---------------- P2: C = A·V (warps role 2,3; TQ=6 x TV=8 as 2x float4) ----------------
    if (role >= 2) {
        const int t  = role - 2;
        const int vt = lane & 7;               // v0 = 4*vt, second group +32
        const int v0 = vt << 2;
        const int qq = (lane >> 3) * 6;
        float4 c[6][2];
#pragma unroll
        for (int i = 0; i < 6; ++i) {
            c[i][0] = make_float4(0.f, 0.f, 0.f, 0.f);
            c[i][1] = make_float4(0.f, 0.f, 0.f, 0.f);
        }
#pragma unroll 4
        for (int k = 0; k < L_; ++k) {
            const float4 va = *reinterpret_cast<const float4*>(&sV[t][k * DV_ + v0]);
            const float4 vb = *reinterpret_cast<const float4*>(&sV[t][k * DV_ + v0 + 32]);
#pragma unroll
            for (int i = 0; i < 6; ++i) {
                const float a = sA[t][(qq + i) * SA + k];
                c[i][0].x = fmaf(a, va.x, c[i][0].x);
                c[i][0].y = fmaf(a, va.y, c[i][0].y);
                c[i][0].z = fmaf(a, va.z, c[i][0].z);
                c[i][0].w = fmaf(a, va.w, c[i][0].w);
                c[i][1].x = fmaf(a, vb.x, c[i][1].x);
                c[i][1].y = fmaf(a, vb.y, c[i][1].y);
                c[i][1].z = fmaf(a, vb.z, c[i][1].z);
                c[i][1].w = fmaf(a, vb.w, c[i][1].w);
            }
        }
        float* C = Cg + (size_t)(2 * bid + t) * QK_;
#pragma unroll
        for (int i = 0; i < 6; ++i) {
            *reinterpret_cast<float4*>(&C[(qq + i) * DV_ + v0])      = c[i][0];
            *reinterpret_cast<float4*>(&C[(qq + i) * DV_ + v0 + 32]) = c[i][1];
        }
    }
}

extern "C" void kernel_launch(void* const* d_in, const int* in_sizes, int n_in,
                              void* d_out, int out_size)
{
    (void)in_sizes; (void)n_in; (void)out_size;
    const float* Q  = (const float*)d_in[0];
    const float* K  = (const float*)d_in[1];
    const float* V  = (const float*)d_in[2];
    const float* Mm = (const float*)d_in[3];
    const float* Ra = (const float*)d_in[4];
    float* ctx    = (float*)d_out;                 // (context, scores) concatenated
    float* scores = (float*)d_out + CTX_ELEMS;
    satt_kernel<<<NB_, 128>>>(Q, K, V, Mm, Ra, ctx, scores);
}

// round 6
// speedup vs baseline: 1.0295x; 1.0295x over previous
#include <cuda_runtime.h>

// Problem constants (B=16, N=325, H=8, L=24, DK=DV=64)
#define L_    24
#define DK_   64
#define DV_   64
#define BNH_  41600
#define QK_   (L_ * DK_)          /* 1536 floats per Q/K/V tile */
#define MS_   (L_ * L_)           /* 576 floats per mask/res/scores tile */

#define SQ  68                    /* padded row stride for Q/K smem */
#define SS  28                    /* padded row stride for scores/attn [q][k] */

static const long long CTX_ELEMS = (long long)BNH_ * QK_;   // 63,897,600

__global__ __launch_bounds__(128, 8)
void satt_kernel(const float* __restrict__ Qg, const float* __restrict__ Kg,
                 const float* __restrict__ Vg, const float* __restrict__ Mg,
                 const float* __restrict__ Rg,
                 float* __restrict__ Cg, float* __restrict__ Sg)
{
    __shared__ float sQ[L_ * SQ];
    __shared__ float sK[L_ * SQ];
    __shared__ float sV[L_ * DV_];      // no pad: all accesses row-wise
    __shared__ float sS[L_ * SS];       // raw masked scores, natural [q][k]
    __shared__ float sMR[2 * MS_];      // mask | res;  later reused as sA
    __shared__ float sPmax[2 * 32];
    __shared__ float sPsum[2 * 32];

    float* const sM = sMR;
    float* const sR = sMR + MS_;
    float* const sA = sMR;              // alias: valid once mask/res are dead

    const int tid  = threadIdx.x;
    const int wid  = tid >> 5;
    const int lane = tid & 31;
    const int bid  = blockIdx.x;
    const int vw   = wid ^ (bid & 3);   // logical role, rotated for SMSP balance
    const size_t qoff = (size_t)bid * QK_;
    const size_t moff = (size_t)bid * MS_;

    // ---------- S0: front-batched loads of Q, K, V, mask, res ----------
    {
        const float4* Q4 = reinterpret_cast<const float4*>(Qg + qoff);
        const float4* K4 = reinterpret_cast<const float4*>(Kg + qoff);
        const float4* V4 = reinterpret_cast<const float4*>(Vg + qoff);
#pragma unroll
        for (int it = 0; it < 3; ++it) {
            int e = tid + it * 128;          // 0..383
            int q = e >> 4;
            int d = (e & 15) << 2;
            *reinterpret_cast<float4*>(&sQ[q * SQ + d]) = Q4[e];
            *reinterpret_cast<float4*>(&sK[q * SQ + d]) = K4[e];
            reinterpret_cast<float4*>(sV)[e] = V4[e];
        }
        const float4* M4 = reinterpret_cast<const float4*>(Mg + moff);
        const float4* R4 = reinterpret_cast<const float4*>(Rg + moff);
        reinterpret_cast<float4*>(sM)[tid] = M4[tid];
        reinterpret_cast<float4*>(sR)[tid] = R4[tid];
        if (tid < 16) {
            reinterpret_cast<float4*>(sM)[tid + 128] = M4[tid + 128];
            reinterpret_cast<float4*>(sR)[tid + 128] = R4[tid + 128];
        }
    }
    __syncthreads();

    // ---------- P1: QK^T on warps {0,1} (12x24 each, TQ=3 x TK=3/lane) + fused epilogue ----------
    if (vw < 2) {
        const int q0 = vw * 12 + (lane >> 3) * 3;
        const int k0 = (lane & 7) * 3;
        float acc[3][3] = {};
#pragma unroll
        for (int d = 0; d < DK_; d += 4) {
            float4 qv[3], kv[3];
#pragma unroll
            for (int i = 0; i < 3; ++i) qv[i] = *reinterpret_cast<const float4*>(&sQ[(q0 + i) * SQ + d]);
#pragma unroll
            for (int j = 0; j < 3; ++j) kv[j] = *reinterpret_cast<const float4*>(&sK[(k0 + j) * SQ + d]);
#pragma unroll
            for (int i = 0; i < 3; ++i)
#pragma unroll
                for (int j = 0; j < 3; ++j) {
                    acc[i][j] = fmaf(qv[i].x, kv[j].x, acc[i][j]);
                    acc[i][j] = fmaf(qv[i].y, kv[j].y, acc[i][j]);
                    acc[i][j] = fmaf(qv[i].z, kv[j].z, acc[i][j]);
                    acc[i][j] = fmaf(qv[i].w, kv[j].w, acc[i][j]);
                }
        }
        // epilogue: scale + res + mask -> raw scores, natural layout
#pragma unroll
        for (int i = 0; i < 3; ++i) {
            const int q = q0 + i;
#pragma unroll
            for (int j = 0; j < 3; ++j) {
                const int k = k0 + j;
                float s = fmaf(acc[i][j], 0.125f, sR[q * L_ + k]);
                if (sM[q * L_ + k] > 0.5f) s = -1e9f;
                sS[q * SS + k] = s;
            }
        }
    }
    __syncthreads();

    // ---------- P2: overlap — warps{0,1}: softmax over q; warps{2,3}: raw scores -> global ----------
    const int r  = vw & 1;              // sub-role within pair
    float v[12];
    if (vw < 2) {
        if (lane < L_) {
#pragma unroll
            for (int i = 0; i < 12; ++i) v[i] = sS[(r * 12 + i) * SS + lane];
            float m = v[0];
#pragma unroll
            for (int i = 1; i < 12; ++i) m = fmaxf(m, v[i]);
            sPmax[r * 32 + lane] = m;
        }
    } else {
        const int hw = r * 32 + lane;    // 0..63
        float4* S4 = reinterpret_cast<float4*>(Sg + moff);
#pragma unroll
        for (int it = 0; it < 2; ++it) {
            int f = hw + it * 64;        // 0..127
            int q = f / 6, k = (f % 6) * 4;
            S4[f] = *reinterpret_cast<const float4*>(&sS[q * SS + k]);
        }
    }
    __syncthreads();

    if (vw < 2) {
        if (lane < L_) {
            const float m = fmaxf(sPmax[lane], sPmax[32 + lane]);
            float s = 0.0f;
#pragma unroll
            for (int i = 0; i < 12; ++i) { v[i] = __expf(v[i] - m); s += v[i]; }
            sPsum[r * 32 + lane] = s;
        }
    } else {
        const int hw = r * 32 + lane;
        if (hw < 16) {
            int f = hw + 128;            // 128..143
            int q = f / 6, k = (f % 6) * 4;
            float4* S4 = reinterpret_cast<float4*>(Sg + moff);
            S4[f] = *reinterpret_cast<const float4*>(&sS[q * SS + k]);
        }
    }
    __syncthreads();

    if (vw < 2 && lane < L_) {
        const float z = sPsum[lane] + sPsum[32 + lane];
        const float w = __fdividef(1.0f, z);
#pragma unroll
        for (int i = 0; i < 12; ++i) sA[(r * 12 + i) * SS + lane] = v[i] * w;
    }
    __syncthreads();

    // ---------- P3: C = A·V on all 4 warps (each 24q x 16v; lane grid 8qg x 4vg; TQ=3, TV=4)
    //             attn read as float4 rows (bank-perfect with stride 28), V as float4 ----------
    {
        const int q0 = (lane >> 2) * 3;                // 8 q-groups of 3
        const int v0 = vw * 16 + (lane & 3) * 4;       // warp-contiguous 16-wide v slice
        float4 c[3];
#pragma unroll
        for (int i = 0; i < 3; ++i) c[i] = make_float4(0.f, 0.f, 0.f, 0.f);

#pragma unroll
        for (int kk = 0; kk < L_; kk += 4) {
            float4 a[3];
#pragma unroll
            for (int i = 0; i < 3; ++i)
                a[i] = *reinterpret_cast<const float4*>(&sA[(q0 + i) * SS + kk]);
            float4 vr[4];
#pragma unroll
            for (int m = 0; m < 4; ++m)
                vr[m] = *reinterpret_cast<const float4*>(&sV[(kk + m) * DV_ + v0]);
#pragma unroll
            for (int i = 0; i < 3; ++i) {
                c[i].x = fmaf(a[i].x, vr[0].x, c[i].x);
                c[i].y = fmaf(a[i].x, vr[0].y, c[i].y);
                c[i].z = fmaf(a[i].x, vr[0].z, c[i].z);
                c[i].w = fmaf(a[i].x, vr[0].w, c[i].w);
                c[i].x = fmaf(a[i].y, vr[1].x, c[i].x);
                c[i].y = fmaf(a[i].y, vr[1].y, c[i].y);
                c[i].z = fmaf(a[i].y, vr[1].z, c[i].z);
                c[i].w = fmaf(a[i].y, vr[1].w, c[i].w);
                c[i].x = fmaf(a[i].z, vr[2].x, c[i].x);
                c[i].y = fmaf(a[i].z, vr[2].y, c[i].y);
                c[i].z = fmaf(a[i].z, vr[2].z, c[i].z);
                c[i].w = fmaf(a[i].z, vr[2].w, c[i].w);
                c[i].x = fmaf(a[i].w, vr[3].x, c[i].x);
                c[i].y = fmaf(a[i].w, vr[3].y, c[i].y);
                c[i].z = fmaf(a[i].w, vr[3].z, c[i].z);
                c[i].w = fmaf(a[i].w, vr[3].w, c[i].w);
            }
        }
        float* C = Cg + qoff;
#pragma unroll
        for (int i = 0; i < 3; ++i)
            *reinterpret_cast<float4*>(&C[(q0 + i) * DV_ + v0]) = c[i];
    }
}

extern "C" void kernel_launch(void* const* d_in, const int* in_sizes, int n_in,
                              void* d_out, int out_size)
{
    (void)in_sizes; (void)n_in; (void)out_size;
    const float* Q  = (const float*)d_in[0];
    const float* K  = (const float*)d_in[1];
    const float* V  = (const float*)d_in[2];
    const float* Mm = (const float*)d_in[3];
    const float* Ra = (const float*)d_in[4];
    float* ctx    = (float*)d_out;                 // (context, scores) concatenated
    float* scores = (float*)d_out + CTX_ELEMS;
    satt_kernel<<<BNH_, 128>>>(Q, K, V, Mm, Ra, ctx, scores);
}